// round 8
// baseline (speedup 1.0000x reference)
#include <cuda_runtime.h>

// B=4, H=8, S=2048, D=3 (fixed by reference)
typedef unsigned long long u64;

#define S_LEN   2048
#define QPC     32            // queries per CTA
#define THREADS 128           // 4 key-groups x 32 query slots; 1 query/thread
#define N_CTA   2048          // 32 bh * 64 chunks
#define GROUPS  4
#define KPG     512           // keys per group
#define ITERS   128           // 2 records (4 keys) per body
#define GSTRIDE 6160          // 256*24 + 16 pad
#define OUT_HALF (32 * S_LEN * 3)
#define SMEM_BYTES (GROUPS * GSTRIDE)   // 24640 B -> 9 CTAs/SM (smem- and reg-capped)

__device__ __forceinline__ u64 fma2(u64 a, u64 b, u64 c) {
    u64 d; asm("fma.rn.f32x2 %0, %1, %2, %3;" : "=l"(d) : "l"(a), "l"(b), "l"(c));
    return d;
}
__device__ __forceinline__ u64 mul2(u64 a, u64 b) {
    u64 d; asm("mul.rn.f32x2 %0, %1, %2;" : "=l"(d) : "l"(a), "l"(b));
    return d;
}
__device__ __forceinline__ u64 add2(u64 a, u64 b) {
    u64 d; asm("add.rn.f32x2 %0, %1, %2;" : "=l"(d) : "l"(a), "l"(b));
    return d;
}
__device__ __forceinline__ u64 ex2_2(u64 x) {
    u64 r;
    asm("{\n\t"
        ".reg .f32 lo, hi;\n\t"
        "mov.b64 {lo, hi}, %1;\n\t"
        "ex2.approx.f32 lo, lo;\n\t"
        "ex2.approx.f32 hi, hi;\n\t"
        "mov.b64 %0, {lo, hi};\n\t"
        "}" : "=l"(r) : "l"(x));
    return r;
}
__device__ __forceinline__ u64 pack2(float lo, float hi) {
    u64 r; asm("mov.b64 %0, {%1, %2};" : "=l"(r) : "f"(lo), "f"(hi));
    return r;
}
__device__ __forceinline__ void unpack2(u64 v, float& lo, float& hi) {
    asm("mov.b64 {%0, %1}, %2;" : "=f"(lo), "=f"(hi) : "l"(v));
}
__device__ __forceinline__ float rcpa(float x) {
    float r; asm("rcp.approx.f32 %0, %1;" : "=f"(r) : "f"(x));
    return r;
}
__device__ __forceinline__ u64 lds64(unsigned addr) {
    u64 v; asm("ld.shared.b64 %0, [%1];" : "=l"(v) : "r"(addr));
    return v;
}

__global__ __launch_bounds__(THREADS, 9)
void attn3d_kernel(const float* __restrict__ x,
                   const float* __restrict__ Wq,
                   const float* __restrict__ Wk,
                   const float* __restrict__ Wv,
                   float* __restrict__ out)
{
    extern __shared__ float sm[];
    float* red = sm;   // aliases x region after post-loop barrier (512 floats)

    const int tid   = threadIdx.x;
    const int cta   = blockIdx.x;
    const int bh    = cta >> 6;        // 64 chunks per (b,h)
    const int chunk = cta & 63;
    const int b     = bh >> 3;
    const int h     = bh & 7;

    const float* xb = x + (size_t)b * S_LEN * 3;

    // ---- Fill smem: 2-key records [x0 pair, x1 pair, x2 pair], 24B each ----
    #pragma unroll
    for (int i = 0; i < S_LEN / THREADS; ++i) {
        const int k  = tid + i * THREADS;
        const int g  = k >> 9;             // key group (512 keys each)
        const int jc = k & 511;
        const int j  = jc >> 1;            // record in group
        const int c  = jc & 1;             // lane in record
        float* rec = reinterpret_cast<float*>(
            reinterpret_cast<char*>(sm) + g * GSTRIDE + j * 24 + c * 4);
        rec[0] = xb[k * 3 + 0];
        rec[2] = xb[k * 3 + 1];
        rec[4] = xb[k * 3 + 2];
    }

    // ---- 1 query per thread; fold Wq*Wk*scale; no shift (range-safe, validated) ----
    const int g  = tid >> 5;          // key group == warp id
    const int ql = tid & 31;          // query slot
    const float* wq = Wq + h * 9;
    const float* wk = Wk + h * 9;
    const float RS = 0.57735026918962576f * 1.4426950408889634f;

    const int sq = chunk * QPC + ql;
    const float xq0 = xb[sq * 3 + 0];
    const float xq1 = xb[sq * 3 + 1];
    const float xq2 = xb[sq * 3 + 2];
    const float q0 = xq0 * wq[0] + xq1 * wq[3] + xq2 * wq[6];
    const float q1 = xq0 * wq[1] + xq1 * wq[4] + xq2 * wq[7];
    const float q2 = xq0 * wq[2] + xq1 * wq[5] + xq2 * wq[8];
    const float a0 = RS * (q0 * wk[0] + q1 * wk[1] + q2 * wk[2]);
    const float a1 = RS * (q0 * wk[3] + q1 * wk[4] + q2 * wk[5]);
    const float a2 = RS * (q0 * wk[6] + q1 * wk[7] + q2 * wk[8]);
    const u64 q0p = pack2(a0, a0);
    const u64 q1p = pack2(a1, a1);
    const u64 q2p = pack2(a2, a2);

    __syncthreads();

    unsigned sbase;
    asm("{ .reg .u64 t; cvta.to.shared.u64 t, %1; cvt.u32.u64 %0, t; }"
        : "=r"(sbase) : "l"(sm));
    unsigned p = sbase + g * GSTRIDE;

    u64 lacc = 0ull, t0 = 0ull, t1 = 0ull, t2 = 0ull;

    // ---- Inner loop: 2 independent records (4 keys) per body ----
    #pragma unroll 2
    for (int r = 0; r < ITERS; ++r) {
        const u64 A0 = lds64(p);
        const u64 A1 = lds64(p + 8);
        const u64 A2 = lds64(p + 16);
        const u64 B0 = lds64(p + 24);
        const u64 B1 = lds64(p + 32);
        const u64 B2 = lds64(p + 40);
        p += 48;
        const u64 dA = fma2(q0p, A0, fma2(q1p, A1, mul2(q2p, A2)));
        const u64 dB = fma2(q0p, B0, fma2(q1p, B1, mul2(q2p, B2)));
        const u64 pA = ex2_2(dA);
        const u64 pB = ex2_2(dB);
        lacc = add2(lacc, add2(pA, pB));
        t0   = fma2(pA, A0, fma2(pB, B0, t0));
        t1   = fma2(pA, A1, fma2(pB, B1, t1));
        t2   = fma2(pA, A2, fma2(pB, B2, t2));
    }

    // ---- All reads done; alias smem for reduction ----
    __syncthreads();
    {
        float a, c;
        unpack2(lacc, a, c); red[0 * 128 + g * 32 + ql] = a + c;
        unpack2(t0,   a, c); red[1 * 128 + g * 32 + ql] = a + c;
        unpack2(t1,   a, c); red[2 * 128 + g * 32 + ql] = a + c;
        unpack2(t2,   a, c); red[3 * 128 + g * 32 + ql] = a + c;
    }
    __syncthreads();

    // ---- 4-way group merge + Wv projection + write both output copies ----
    if (tid < QPC) {
        const float L  = red[0 * 128 + tid] + red[0 * 128 + 32 + tid]
                       + red[0 * 128 + 64 + tid] + red[0 * 128 + 96 + tid];
        const float T0 = red[1 * 128 + tid] + red[1 * 128 + 32 + tid]
                       + red[1 * 128 + 64 + tid] + red[1 * 128 + 96 + tid];
        const float T1 = red[2 * 128 + tid] + red[2 * 128 + 32 + tid]
                       + red[2 * 128 + 64 + tid] + red[2 * 128 + 96 + tid];
        const float T2 = red[3 * 128 + tid] + red[3 * 128 + 32 + tid]
                       + red[3 * 128 + 64 + tid] + red[3 * 128 + 96 + tid];
        const float inv = rcpa(L);
        const float* wv = Wv + h * 9;
        const float r0 = (T0 * wv[0] + T1 * wv[3] + T2 * wv[6]) * inv;
        const float r1 = (T0 * wv[1] + T1 * wv[4] + T2 * wv[7]) * inv;
        const float r2 = (T0 * wv[2] + T1 * wv[5] + T2 * wv[8]) * inv;
        const int base = (bh * S_LEN + chunk * QPC + tid) * 3;
        out[base + 0] = r0;
        out[base + 1] = r1;
        out[base + 2] = r2;
        out[OUT_HALF + base + 0] = r0;
        out[OUT_HALF + base + 1] = r1;
        out[OUT_HALF + base + 2] = r2;
    }
}

extern "C" void kernel_launch(void* const* d_in, const int* in_sizes, int n_in,
                              void* d_out, int out_size)
{
    const float* x  = (const float*)d_in[0];
    const float* Wq = (const float*)d_in[1];
    const float* Wk = (const float*)d_in[2];
    const float* Wv = (const float*)d_in[3];
    float* out = (float*)d_out;

    cudaFuncSetAttribute(attn3d_kernel,
                         cudaFuncAttributeMaxDynamicSharedMemorySize, SMEM_BYTES);
    attn3d_kernel<<<N_CTA, THREADS, SMEM_BYTES>>>(x, Wq, Wk, Wv, out);
}